// round 11
// baseline (speedup 1.0000x reference)
#include <cuda_runtime.h>
#include <cuda_fp16.h>
#include <cstdint>

#define N_ROWS 200000
#define HID    512
#define HHALF  256
#define NG     2000
#define MROWS  64
#define NTHREADS 256

// smem layout (per CTA)
#define OFF_ALPHA 0          // 64 floats
#define OFF_RSUM  256        // 64 floats
#define OFF_A     1024       // 4 stages x 4096B (paired-row swizzled fp16, K=32)
#define A_STG     4096
#define OFF_B     17408      // 3 stages x 32768B (256 rows x 128B fp16, K=64 pair)
#define B_STG     32768
#define SMEM_TOTAL 115712

__device__ __half g_W1h[HHALF * HID];

// ---------------- helpers ----------------
__device__ __forceinline__ uint32_t smem_u32(const void* p) {
    uint32_t a;
    asm("{ .reg .u64 t; cvta.to.shared.u64 t, %1; cvt.u32.u64 %0, t; }" : "=r"(a) : "l"(p));
    return a;
}
#define LDSM4(r, a) asm volatile("ldmatrix.sync.aligned.m8n8.x4.shared.b16 {%0,%1,%2,%3}, [%4];" \
    : "=r"((r)[0]),"=r"((r)[1]),"=r"((r)[2]),"=r"((r)[3]) : "r"(a))
#define MMA16816(d, a, b0, b1) asm volatile( \
    "mma.sync.aligned.m16n8k16.row.col.f32.f16.f16.f32 " \
    "{%0,%1,%2,%3}, {%4,%5,%6,%7}, {%8,%9}, {%0,%1,%2,%3};" \
    : "+f"((d)[0]),"+f"((d)[1]),"+f"((d)[2]),"+f"((d)[3]) \
    : "r"((a)[0]),"r"((a)[1]),"r"((a)[2]),"r"((a)[3]), "r"(b0),"r"(b1))
#define CPASYNC16(dst, src) asm volatile("cp.async.cg.shared.global [%0], [%1], 16;" :: "r"(dst), "l"(src) : "memory")
#define CPCOMMIT() asm volatile("cp.async.commit_group;" ::: "memory")
#define CPWAIT1()  asm volatile("cp.async.wait_group 1;" ::: "memory")

__device__ __forceinline__ uint32_t pack_f16x2(float e_lo, float e_hi) {
    uint32_t r;
    asm("cvt.rn.f16x2.f32 %0, %1, %2;" : "=r"(r) : "f"(e_hi), "f"(e_lo));
    return r;
}
__device__ __forceinline__ float silu_f(float z) { return __fdividef(z, 1.0f + __expf(-z)); }

// ---------------- prep kernel ----------------
__global__ void prep_kernel(const float* __restrict__ W1, float* __restrict__ out) {
    int i = blockIdx.x * blockDim.x + threadIdx.x;
    if (i < NG) out[i] = 0.0f;
    if (i < HHALF * HID) g_W1h[i] = __float2half(W1[i]);
}

// ---------------- staging ----------------
// B pair (K=64): 256 rows x 128B fp16, XOR-swizzled, into slot st (0..2)
__device__ __forceinline__ void stage_B(uint32_t sbase, int st, int kk, int tid) {
    #pragma unroll
    for (int j = 0; j < 8; ++j) {
        int task = tid + j * 256;
        int n    = task >> 3;
        int unit = task & 7;
        const __half* src = g_W1h + n * HID + kk + unit * 8;
        uint32_t dst = sbase + OFF_B + st * B_STG + n * 128
                     + (((unsigned)(unit ^ (n & 7))) << 4);
        CPASYNC16(dst, src);
    }
}

// LDG one K=32 chunk of h into 2 float4 regs (thread: row tid>>2, k-slice tid&3)
__device__ __forceinline__ void load_h(float4 va[2], const float* __restrict__ h,
                                       int row0, int tid, int chunk) {
    const int ar = tid >> 2;
    const int q  = tid & 3;
    const float* p = h + (size_t)(row0 + ar) * HID + chunk * 32 + q * 8;
    va[0] = __ldg((const float4*)p);
    va[1] = __ldg((const float4*)(p + 4));
}

// convert registers -> A fp16 (stage chunk&3, paired-row layout) + alpha partial
__device__ __forceinline__ void convert_reg(char* smem, const float4 va[2], int chunk,
                                            const float* __restrict__ Ww,
                                            int tid, float& aacc) {
    const int ar = tid >> 2;
    const int q  = tid & 3;
    float4 v0 = va[0], v1 = va[1];
    float4 w0 = __ldg((const float4*)(Ww + chunk * 32 + q * 8));
    float4 w1 = __ldg((const float4*)(Ww + chunk * 32 + q * 8 + 4));
    aacc += v0.x * w0.x + v0.y * w0.y + v0.z * w0.z + v0.w * w0.w
          + v1.x * w1.x + v1.y * w1.y + v1.z * w1.z + v1.w * w1.w;
    uint4 pk = make_uint4(pack_f16x2(v0.x, v0.y), pack_f16x2(v0.z, v0.w),
                          pack_f16x2(v1.x, v1.y), pack_f16x2(v1.z, v1.w));
    uint32_t dst = OFF_A + (chunk & 3) * A_STG + (ar >> 1) * 128
                 + ((unsigned)(((4 * (ar & 1) + q) ^ ((ar >> 1) & 7))) << 4);
    *(uint4*)(smem + dst) = pk;
}

// ---------------- main kernel ----------------
__global__ __launch_bounds__(NTHREADS, 2)
void fused_mma_kernel(
    const float* __restrict__ h,
    const void*  __restrict__ batch_raw,
    const float* __restrict__ b1,
    const float* __restrict__ W2,
    const float* __restrict__ b2,
    const float* __restrict__ Ww,
    const float* __restrict__ bw,
    float* __restrict__ out)
{
    extern __shared__ char smem[];
    const uint32_t sbase = smem_u32(smem);
    const int tid = threadIdx.x;
    const int wid = tid >> 5, lid = tid & 31;
    const int row0 = blockIdx.x * MROWS;

    float* alps = (float*)(smem + OFF_ALPHA);
    float* rsum = (float*)(smem + OFF_RSUM);
    if (tid < MROWS) rsum[tid] = 0.0f;

    const bool is64 = (((const int*)batch_raw)[N_ROWS - 1] == 0);

    // warp layout: 2 x 4 grid of 32x64 tiles
    const int wm = wid >> 2;
    const int wn = wid & 3;
    const int arow_lane = wm * 32 + (lid & 15);
    const int a_uhalf   = lid >> 4;
    const int b_nlane   = wn * 64 + (lid & 7) + ((lid >> 4) << 3);
    const int b_uhalf   = (lid >> 3) & 1;

    float acc[2][8][4];
    #pragma unroll
    for (int a = 0; a < 2; ++a)
        #pragma unroll
        for (int b = 0; b < 8; ++b)
            #pragma unroll
            for (int c = 0; c < 4; ++c) acc[a][b][c] = 0.0f;

    float aacc = 0.0f;
    float4 va0[2], va1[2];

// MMA over one K=32 chunk: A stage AST, B slot BST, k-half KH within B pair
#define MMA_CHUNK(AST, BST, KH)                                                     \
    {                                                                               \
        const uint32_t abase = sbase + OFF_A + (AST) * A_STG;                       \
        const uint32_t bbase = sbase + OFF_B + (BST) * B_STG;                       \
        _Pragma("unroll")                                                           \
        for (int ks = 0; ks < 2; ++ks) {                                            \
            uint32_t ah[2][4], bb[4][4];                                            \
            _Pragma("unroll")                                                       \
            for (int mt = 0; mt < 2; ++mt) {                                        \
                int r = arow_lane + mt * 16;                                        \
                uint32_t u = (uint32_t)((4 * (r & 1) + ks * 2 + a_uhalf)            \
                                        ^ ((r >> 1) & 7));                          \
                LDSM4(ah[mt], abase + (unsigned)(r >> 1) * 128 + (u << 4));         \
            }                                                                       \
            _Pragma("unroll")                                                       \
            for (int p = 0; p < 4; ++p) {                                           \
                int n = b_nlane + p * 16;                                           \
                uint32_t u = (uint32_t)(((KH) * 4 + ks * 2 + b_uhalf) ^ (n & 7));   \
                LDSM4(bb[p], bbase + (unsigned)n * 128 + (u << 4));                 \
            }                                                                       \
            _Pragma("unroll")                                                       \
            for (int mt = 0; mt < 2; ++mt)                                          \
                _Pragma("unroll")                                                   \
                for (int nt = 0; nt < 8; ++nt)                                      \
                    MMA16816(acc[mt][nt], ah[mt],                                   \
                             bb[nt >> 1][(nt & 1) * 2], bb[nt >> 1][(nt & 1) * 2 + 1]); \
        }                                                                           \
    }

    // ---------------- prologue ----------------
    // B pairs 0 and 1 in flight (slots 0,1); h chunks 0,1 via registers
    stage_B(sbase, 0, 0, tid);
    CPCOMMIT();
    stage_B(sbase, 1, 64, tid);
    CPCOMMIT();
    load_h(va0, h, row0, tid, 0);
    load_h(va1, h, row0, tid, 1);
    convert_reg(smem, va0, 0, Ww, tid, aacc);
    convert_reg(smem, va1, 1, Ww, tid, aacc);
    CPWAIT1();                 // pair 0 complete (pair 1 may pend)
    __syncthreads();

    // ---------------- main loop: 8 iterations of K=64 ----------------
    for (int i = 0; i < 8; ++i) {
        const int c0 = 2 * i;
        // stage B pair i+2 (slot (i+2)%3), distance 2 iterations
        if (i < 6) stage_B(sbase, (i + 2) % 3, (i + 2) * 64, tid);
        CPCOMMIT();            // unconditional: uniform group counting
        // issue h LDGs for chunks c0+2, c0+3 (converted later this iter)
        if (i < 7) {
            load_h(va0, h, row0, tid, c0 + 2);
            load_h(va1, h, row0, tid, c0 + 3);
        }

        MMA_CHUNK(c0 & 3, i % 3, 0);
        if (i < 7) convert_reg(smem, va0, c0 + 2, Ww, tid, aacc);
        MMA_CHUNK((c0 + 1) & 3, i % 3, 1);
        if (i < 7) convert_reg(smem, va1, c0 + 3, Ww, tid, aacc);

        CPWAIT1();             // B pair i+1 guaranteed in (pair i+2 may pend)
        __syncthreads();
    }

    // ---------------- epilogue ----------------
    aacc += __shfl_xor_sync(0xffffffffu, aacc, 1);
    aacc += __shfl_xor_sync(0xffffffffu, aacc, 2);
    if ((tid & 3) == 0) alps[tid >> 2] = aacc;

    {
        #pragma unroll
        for (int mt = 0; mt < 2; ++mt) {
            float p0 = 0.0f, p1 = 0.0f;
            #pragma unroll
            for (int nt = 0; nt < 8; ++nt) {
                int col = wn * 64 + nt * 8 + 2 * (lid & 3);
                float bA = __ldg(b1 + col), bB = __ldg(b1 + col + 1);
                float wA = __ldg(W2 + col), wB = __ldg(W2 + col + 1);
                p0 += silu_f(acc[mt][nt][0] + bA) * wA + silu_f(acc[mt][nt][1] + bB) * wB;
                p1 += silu_f(acc[mt][nt][2] + bA) * wA + silu_f(acc[mt][nt][3] + bB) * wB;
            }
            p0 += __shfl_xor_sync(0xffffffffu, p0, 1);
            p0 += __shfl_xor_sync(0xffffffffu, p0, 2);
            p1 += __shfl_xor_sync(0xffffffffu, p1, 1);
            p1 += __shfl_xor_sync(0xffffffffu, p1, 2);
            if ((lid & 3) == 0) {
                int r = wm * 32 + mt * 16 + (lid >> 2);
                atomicAdd(&rsum[r], p0);
                atomicAdd(&rsum[r + 8], p1);
            }
        }
    }
    __syncthreads();

    if (tid < MROWS) {
        const int row = tid, grow = row0 + row;
        const float b2v = __ldg(b2), bwv = __ldg(bw);
        float val = (rsum[row] + b2v) * (alps[row] + bwv);
        int g = is64 ? (int)((const long long*)batch_raw)[grow]
                     : ((const int*)batch_raw)[grow];
        float tot = 0.0f;
        #pragma unroll
        for (int k2 = 0; k2 < 32; ++k2) {
            float vk = __shfl_sync(0xffffffffu, val, k2);
            int   gk = __shfl_sync(0xffffffffu, g, k2);
            if (gk == g) tot += vk;
        }
        int gp = __shfl_up_sync(0xffffffffu, g, 1);
        if (lid == 0 || g != gp) atomicAdd(out + g, tot);
    }
#undef MMA_CHUNK
}

// ---------------- launch ----------------
extern "C" void kernel_launch(void* const* d_in, const int* in_sizes, int n_in,
                              void* d_out, int out_size) {
    const float* h     = (const float*)d_in[0];
    const void*  batch = d_in[3];
    const float* W1    = (const float*)d_in[5];
    const float* b1    = (const float*)d_in[6];
    const float* W2    = (const float*)d_in[7];
    const float* b2    = (const float*)d_in[8];
    const float* Ww    = (const float*)d_in[9];
    const float* bw    = (const float*)d_in[10];
    float* out = (float*)d_out;

    cudaFuncSetAttribute(fused_mma_kernel,
                         cudaFuncAttributeMaxDynamicSharedMemorySize, SMEM_TOTAL);

    prep_kernel<<<(HHALF * HID) / 256, 256>>>(W1, out);

    int grid = N_ROWS / MROWS;   // 3125, exact
    fused_mma_kernel<<<grid, NTHREADS, SMEM_TOTAL>>>(h, batch, b1, W2, b2, Ww, bw, out);
}

// round 12
// speedup vs baseline: 1.0380x; 1.0380x over previous
#include <cuda_runtime.h>
#include <cuda_fp16.h>
#include <cstdint>

#define N_ROWS 200000
#define HID    512
#define HHALF  256
#define NG     2000
#define MROWS  64
#define NTHREADS 256

// smem layout (per CTA)
#define OFF_ALPHA 0          // 64 floats
#define OFF_RSUM  256        // 64 floats
#define OFF_A     1024       // 4 stages x 4096B (paired-row swizzled fp16, K=32)
#define A_STG     4096
#define OFF_B     17408      // 3 stages x 32768B (256 rows x 128B fp16, K=64 pair)
#define B_STG     32768
#define SMEM_TOTAL 115712

__device__ __half g_W1h[HHALF * HID];

// ---------------- helpers ----------------
__device__ __forceinline__ uint32_t smem_u32(const void* p) {
    uint32_t a;
    asm("{ .reg .u64 t; cvta.to.shared.u64 t, %1; cvt.u32.u64 %0, t; }" : "=r"(a) : "l"(p));
    return a;
}
#define LDSM4(r, a) asm volatile("ldmatrix.sync.aligned.m8n8.x4.shared.b16 {%0,%1,%2,%3}, [%4];" \
    : "=r"((r)[0]),"=r"((r)[1]),"=r"((r)[2]),"=r"((r)[3]) : "r"(a))
#define MMA16816(d, a, b0, b1) asm volatile( \
    "mma.sync.aligned.m16n8k16.row.col.f32.f16.f16.f32 " \
    "{%0,%1,%2,%3}, {%4,%5,%6,%7}, {%8,%9}, {%0,%1,%2,%3};" \
    : "+f"((d)[0]),"+f"((d)[1]),"+f"((d)[2]),"+f"((d)[3]) \
    : "r"((a)[0]),"r"((a)[1]),"r"((a)[2]),"r"((a)[3]), "r"(b0),"r"(b1))
#define CPASYNC16(dst, src) asm volatile("cp.async.cg.shared.global [%0], [%1], 16;" :: "r"(dst), "l"(src) : "memory")
#define CPCOMMIT() asm volatile("cp.async.commit_group;" ::: "memory")
#define CPWAIT1()  asm volatile("cp.async.wait_group 1;" ::: "memory")

__device__ __forceinline__ uint32_t pack_f16x2(float e_lo, float e_hi) {
    uint32_t r;
    asm("cvt.rn.f16x2.f32 %0, %1, %2;" : "=r"(r) : "f"(e_hi), "f"(e_lo));
    return r;
}
__device__ __forceinline__ float silu_f(float z) { return __fdividef(z, 1.0f + __expf(-z)); }

// ---------------- prep kernel ----------------
__global__ void prep_kernel(const float* __restrict__ W1, float* __restrict__ out) {
    int i = blockIdx.x * blockDim.x + threadIdx.x;
    if (i < NG) out[i] = 0.0f;
    if (i < HHALF * HID) g_W1h[i] = __float2half(W1[i]);
}

// ---------------- staging ----------------
// B pair (K=64): 256 rows x 128B fp16, XOR-swizzled, into slot st (0..2)
__device__ __forceinline__ void stage_B(uint32_t sbase, int st, int kk, int tid) {
    #pragma unroll
    for (int j = 0; j < 8; ++j) {
        int task = tid + j * 256;
        int n    = task >> 3;
        int unit = task & 7;
        const __half* src = g_W1h + n * HID + kk + unit * 8;
        uint32_t dst = sbase + OFF_B + st * B_STG + n * 128
                     + (((unsigned)(unit ^ (n & 7))) << 4);
        CPASYNC16(dst, src);
    }
}

// LDG one K=32 chunk of h (thread: row tid>>2 via hrow, k-slice tid&3 folded in hrow)
__device__ __forceinline__ void load_h(float4 va[2], const float* hrow, int chunk) {
    const float* p = hrow + chunk * 32;
    va[0] = __ldg((const float4*)p);
    va[1] = __ldg((const float4*)(p + 4));
}

// convert registers -> A fp16 (stage chunk&3, paired-row layout) + alpha partial
__device__ __forceinline__ void convert_reg(char* smem, const float4 va[2], int chunk,
                                            const float* __restrict__ Ww,
                                            int tid, float& aacc) {
    const int ar = tid >> 2;
    const int q  = tid & 3;
    float4 v0 = va[0], v1 = va[1];
    float4 w0 = __ldg((const float4*)(Ww + chunk * 32 + q * 8));
    float4 w1 = __ldg((const float4*)(Ww + chunk * 32 + q * 8 + 4));
    aacc += v0.x * w0.x + v0.y * w0.y + v0.z * w0.z + v0.w * w0.w
          + v1.x * w1.x + v1.y * w1.y + v1.z * w1.z + v1.w * w1.w;
    uint4 pk = make_uint4(pack_f16x2(v0.x, v0.y), pack_f16x2(v0.z, v0.w),
                          pack_f16x2(v1.x, v1.y), pack_f16x2(v1.z, v1.w));
    uint32_t dst = OFF_A + (chunk & 3) * A_STG + (ar >> 1) * 128
                 + ((unsigned)(((4 * (ar & 1) + q) ^ ((ar >> 1) & 7))) << 4);
    *(uint4*)(smem + dst) = pk;
}

// ---------------- main kernel ----------------
__global__ __launch_bounds__(NTHREADS, 2)
void fused_mma_kernel(
    const float* __restrict__ h,
    const void*  __restrict__ batch_raw,
    const float* __restrict__ b1,
    const float* __restrict__ W2,
    const float* __restrict__ b2,
    const float* __restrict__ Ww,
    const float* __restrict__ bw,
    float* __restrict__ out)
{
    extern __shared__ char smem[];
    const uint32_t sbase = smem_u32(smem);
    const int tid = threadIdx.x;
    const int wid = tid >> 5, lid = tid & 31;
    const int row0 = blockIdx.x * MROWS;

    float* alps = (float*)(smem + OFF_ALPHA);
    float* rsum = (float*)(smem + OFF_RSUM);
    if (tid < MROWS) rsum[tid] = 0.0f;

    const bool is64 = (((const int*)batch_raw)[N_ROWS - 1] == 0);

    // warp layout: 2 x 4 grid of 32x64 tiles
    const int wm = wid >> 2;
    const int wn = wid & 3;
    const int arow_lane = wm * 32 + (lid & 15);
    const int a_uhalf   = lid >> 4;
    const int b_nlane   = wn * 64 + (lid & 7) + ((lid >> 4) << 3);
    const int b_uhalf   = (lid >> 3) & 1;

    // per-thread h row pointer (row tid>>2, k-slice tid&3)
    const float* hrow = h + (size_t)(row0 + (tid >> 2)) * HID + (tid & 3) * 8;

    float acc[2][8][4];
    #pragma unroll
    for (int a = 0; a < 2; ++a)
        #pragma unroll
        for (int b = 0; b < 8; ++b)
            #pragma unroll
            for (int c = 0; c < 4; ++c) acc[a][b][c] = 0.0f;

    float aacc = 0.0f;
    float4 va[2];

// MMA over one K=32 chunk: A stage AST, B slot BST, k-half KH.
// bb[2][4]: B fragments consumed in two 32-col phases to cap live registers.
#define MMA_CHUNK(AST, BST, KH)                                                     \
    {                                                                               \
        const uint32_t abase = sbase + OFF_A + (AST) * A_STG;                       \
        const uint32_t bbase = sbase + OFF_B + (BST) * B_STG;                       \
        _Pragma("unroll")                                                           \
        for (int ks = 0; ks < 2; ++ks) {                                            \
            uint32_t ah[2][4], bb[2][4];                                            \
            _Pragma("unroll")                                                       \
            for (int mt = 0; mt < 2; ++mt) {                                        \
                int r = arow_lane + mt * 16;                                        \
                uint32_t u = (uint32_t)((4 * (r & 1) + ks * 2 + a_uhalf)            \
                                        ^ ((r >> 1) & 7));                          \
                LDSM4(ah[mt], abase + (unsigned)(r >> 1) * 128 + (u << 4));         \
            }                                                                       \
            _Pragma("unroll")                                                       \
            for (int ph = 0; ph < 2; ++ph) {                                        \
                _Pragma("unroll")                                                   \
                for (int p = 0; p < 2; ++p) {                                       \
                    int n = b_nlane + (ph * 2 + p) * 16;                            \
                    uint32_t u = (uint32_t)(((KH) * 4 + ks * 2 + b_uhalf) ^ (n & 7)); \
                    LDSM4(bb[p], bbase + (unsigned)n * 128 + (u << 4));             \
                }                                                                   \
                _Pragma("unroll")                                                   \
                for (int mt = 0; mt < 2; ++mt)                                      \
                    _Pragma("unroll")                                               \
                    for (int j = 0; j < 4; ++j)                                     \
                        MMA16816(acc[mt][ph * 4 + j], ah[mt],                       \
                                 bb[j >> 1][(j & 1) * 2], bb[j >> 1][(j & 1) * 2 + 1]); \
            }                                                                       \
        }                                                                           \
    }

    // ---------------- prologue ----------------
    stage_B(sbase, 0, 0, tid);
    CPCOMMIT();
    stage_B(sbase, 1, 64, tid);
    CPCOMMIT();
    load_h(va, hrow, 0);
    convert_reg(smem, va, 0, Ww, tid, aacc);
    load_h(va, hrow, 1);
    convert_reg(smem, va, 1, Ww, tid, aacc);
    CPWAIT1();                 // B pair 0 complete
    __syncthreads();

    // ---------------- main loop: 8 iterations of K=64 ----------------
    for (int i = 0; i < 8; ++i) {
        const int c0 = 2 * i;
        if (i < 6) stage_B(sbase, (i + 2) % 3, (i + 2) * 64, tid);
        CPCOMMIT();            // uniform group counting
        if (i < 7) load_h(va, hrow, c0 + 2);

        MMA_CHUNK(c0 & 3, i % 3, 0);
        if (i < 7) {
            convert_reg(smem, va, c0 + 2, Ww, tid, aacc);
            load_h(va, hrow, c0 + 3);
        }
        MMA_CHUNK((c0 + 1) & 3, i % 3, 1);
        if (i < 7) convert_reg(smem, va, c0 + 3, Ww, tid, aacc);

        CPWAIT1();             // B pair i+1 guaranteed in
        __syncthreads();
    }

    // ---------------- epilogue ----------------
    aacc += __shfl_xor_sync(0xffffffffu, aacc, 1);
    aacc += __shfl_xor_sync(0xffffffffu, aacc, 2);
    if ((tid & 3) == 0) alps[tid >> 2] = aacc;

    {
        #pragma unroll
        for (int mt = 0; mt < 2; ++mt) {
            float p0 = 0.0f, p1 = 0.0f;
            #pragma unroll
            for (int nt = 0; nt < 8; ++nt) {
                int col = wn * 64 + nt * 8 + 2 * (lid & 3);
                float bA = __ldg(b1 + col), bB = __ldg(b1 + col + 1);
                float wA = __ldg(W2 + col), wB = __ldg(W2 + col + 1);
                p0 += silu_f(acc[mt][nt][0] + bA) * wA + silu_f(acc[mt][nt][1] + bB) * wB;
                p1 += silu_f(acc[mt][nt][2] + bA) * wA + silu_f(acc[mt][nt][3] + bB) * wB;
            }
            p0 += __shfl_xor_sync(0xffffffffu, p0, 1);
            p0 += __shfl_xor_sync(0xffffffffu, p0, 2);
            p1 += __shfl_xor_sync(0xffffffffu, p1, 1);
            p1 += __shfl_xor_sync(0xffffffffu, p1, 2);
            if ((lid & 3) == 0) {
                int r = wm * 32 + mt * 16 + (lid >> 2);
                atomicAdd(&rsum[r], p0);
                atomicAdd(&rsum[r + 8], p1);
            }
        }
    }
    __syncthreads();

    if (tid < MROWS) {
        const int row = tid, grow = row0 + row;
        const float b2v = __ldg(b2), bwv = __ldg(bw);
        float val = (rsum[row] + b2v) * (alps[row] + bwv);
        int g = is64 ? (int)((const long long*)batch_raw)[grow]
                     : ((const int*)batch_raw)[grow];
        float tot = 0.0f;
        #pragma unroll
        for (int k2 = 0; k2 < 32; ++k2) {
            float vk = __shfl_sync(0xffffffffu, val, k2);
            int   gk = __shfl_sync(0xffffffffu, g, k2);
            if (gk == g) tot += vk;
        }
        int gp = __shfl_up_sync(0xffffffffu, g, 1);
        if (lid == 0 || g != gp) atomicAdd(out + g, tot);
    }
#undef MMA_CHUNK
}

// ---------------- launch ----------------
extern "C" void kernel_launch(void* const* d_in, const int* in_sizes, int n_in,
                              void* d_out, int out_size) {
    const float* h     = (const float*)d_in[0];
    const void*  batch = d_in[3];
    const float* W1    = (const float*)d_in[5];
    const float* b1    = (const float*)d_in[6];
    const float* W2    = (const float*)d_in[7];
    const float* b2    = (const float*)d_in[8];
    const float* Ww    = (const float*)d_in[9];
    const float* bw    = (const float*)d_in[10];
    float* out = (float*)d_out;

    cudaFuncSetAttribute(fused_mma_kernel,
                         cudaFuncAttributeMaxDynamicSharedMemorySize, SMEM_TOTAL);

    prep_kernel<<<(HHALF * HID) / 256, 256>>>(W1, out);

    int grid = N_ROWS / MROWS;   // 3125, exact
    fused_mma_kernel<<<grid, NTHREADS, SMEM_TOTAL>>>(h, batch, b1, W2, b2, Ww, bw, out);
}

// round 13
// speedup vs baseline: 1.2767x; 1.2299x over previous
#include <cuda_runtime.h>
#include <cuda_fp16.h>
#include <cstdint>

#define N_ROWS 200000
#define HID    512
#define HHALF  256
#define NG     2000
#define MROWS  64
#define NTHREADS 256

// smem layout (per CTA)
#define OFF_ALPHA 0          // 64 floats
#define OFF_RSUM  256        // 64 floats
#define OFF_A     1024       // 4 stages x 4096B (paired-row swizzled fp16, K=32)
#define A_STG     4096
#define OFF_H     17408      // 4 stages x 8192B (64 rows x 128B fp32, swizzled, K=32)
#define H_STG     8192
#define OFF_B     50176      // 2 stages x 32768B (256 rows x 128B fp16, K=64 pair)
#define B_STG     32768
#define SMEM_TOTAL 115712

__device__ __half g_W1h[HHALF * HID];

// ---------------- helpers ----------------
__device__ __forceinline__ uint32_t smem_u32(const void* p) {
    uint32_t a;
    asm("{ .reg .u64 t; cvta.to.shared.u64 t, %1; cvt.u32.u64 %0, t; }" : "=r"(a) : "l"(p));
    return a;
}
#define LDSM4(r, a) asm volatile("ldmatrix.sync.aligned.m8n8.x4.shared.b16 {%0,%1,%2,%3}, [%4];" \
    : "=r"((r)[0]),"=r"((r)[1]),"=r"((r)[2]),"=r"((r)[3]) : "r"(a))
#define MMA16816(d, a, b0, b1) asm volatile( \
    "mma.sync.aligned.m16n8k16.row.col.f32.f16.f16.f32 " \
    "{%0,%1,%2,%3}, {%4,%5,%6,%7}, {%8,%9}, {%0,%1,%2,%3};" \
    : "+f"((d)[0]),"+f"((d)[1]),"+f"((d)[2]),"+f"((d)[3]) \
    : "r"((a)[0]),"r"((a)[1]),"r"((a)[2]),"r"((a)[3]), "r"(b0),"r"(b1))
#define CPASYNC16(dst, src) asm volatile("cp.async.cg.shared.global [%0], [%1], 16;" :: "r"(dst), "l"(src) : "memory")
#define CPCOMMIT() asm volatile("cp.async.commit_group;" ::: "memory")
#define CPWAIT0()  asm volatile("cp.async.wait_group 0;" ::: "memory")

__device__ __forceinline__ uint32_t pack_f16x2(float e_lo, float e_hi) {
    uint32_t r;
    asm("cvt.rn.f16x2.f32 %0, %1, %2;" : "=r"(r) : "f"(e_hi), "f"(e_lo));
    return r;
}
__device__ __forceinline__ float silu_f(float z) { return __fdividef(z, 1.0f + __expf(-z)); }

// ---------------- prep kernel ----------------
__global__ void prep_kernel(const float* __restrict__ W1, float* __restrict__ out) {
    int i = blockIdx.x * blockDim.x + threadIdx.x;
    if (i < NG) out[i] = 0.0f;
    if (i < HHALF * HID) g_W1h[i] = __float2half(W1[i]);
}

// ---------------- staging ----------------
// h chunk (K=32): 64 rows x 128B fp32, XOR-swizzled
__device__ __forceinline__ void stage_h(uint32_t sbase, int st, int kk,
                                        const float* __restrict__ h, int row0, int tid) {
    #pragma unroll
    for (int j = 0; j < 2; ++j) {
        int task = tid + j * 256;
        int row  = task >> 3;
        int unit = task & 7;
        const float* src = h + (size_t)(row0 + row) * HID + kk + unit * 4;
        uint32_t dst = sbase + OFF_H + st * H_STG + row * 128
                     + (((unsigned)(unit ^ (row & 7))) << 4);
        CPASYNC16(dst, src);
    }
}

// B pair (K=64): 256 rows x 128B fp16, XOR-swizzled
__device__ __forceinline__ void stage_B(uint32_t sbase, int st, int kk, int tid) {
    #pragma unroll
    for (int j = 0; j < 8; ++j) {
        int task = tid + j * 256;
        int n    = task >> 3;
        int unit = task & 7;
        const __half* src = g_W1h + n * HID + kk + unit * 8;
        uint32_t dst = sbase + OFF_B + st * B_STG + n * 128
                     + (((unsigned)(unit ^ (n & 7))) << 4);
        CPASYNC16(dst, src);
    }
}

// convert h fp32 (stage chunk&3) -> A fp16 (stage chunk&3, paired-row) + alpha partial
__device__ __forceinline__ void convert_chunk(char* smem, int chunk,
                                              const float* __restrict__ Ww,
                                              int tid, float& aacc) {
    const int ar = tid >> 2;
    const int q  = tid & 3;
    const char* hb = smem + OFF_H + (chunk & 3) * H_STG + ar * 128;
    uint32_t u0 = (unsigned)((2 * q)     ^ (ar & 7));
    uint32_t u1 = (unsigned)((2 * q + 1) ^ (ar & 7));
    float4 v0 = *(const float4*)(hb + (u0 << 4));
    float4 v1 = *(const float4*)(hb + (u1 << 4));
    float4 w0 = __ldg((const float4*)(Ww + chunk * 32 + q * 8));
    float4 w1 = __ldg((const float4*)(Ww + chunk * 32 + q * 8 + 4));
    aacc += v0.x * w0.x + v0.y * w0.y + v0.z * w0.z + v0.w * w0.w
          + v1.x * w1.x + v1.y * w1.y + v1.z * w1.z + v1.w * w1.w;
    uint4 pk = make_uint4(pack_f16x2(v0.x, v0.y), pack_f16x2(v0.z, v0.w),
                          pack_f16x2(v1.x, v1.y), pack_f16x2(v1.z, v1.w));
    uint32_t dst = OFF_A + (chunk & 3) * A_STG + (ar >> 1) * 128
                 + ((unsigned)(((4 * (ar & 1) + q) ^ ((ar >> 1) & 7))) << 4);
    *(uint4*)(smem + dst) = pk;
}

// ---------------- main kernel ----------------
__global__ __launch_bounds__(NTHREADS, 2)
void fused_mma_kernel(
    const float* __restrict__ h,
    const void*  __restrict__ batch_raw,
    const float* __restrict__ b1,
    const float* __restrict__ W2,
    const float* __restrict__ b2,
    const float* __restrict__ Ww,
    const float* __restrict__ bw,
    float* __restrict__ out)
{
    extern __shared__ char smem[];
    const uint32_t sbase = smem_u32(smem);
    const int tid = threadIdx.x;
    const int wid = tid >> 5, lid = tid & 31;
    const int row0 = blockIdx.x * MROWS;

    float* alps = (float*)(smem + OFF_ALPHA);
    float* rsum = (float*)(smem + OFF_RSUM);
    if (tid < MROWS) rsum[tid] = 0.0f;

    const bool is64 = (((const int*)batch_raw)[N_ROWS - 1] == 0);

    // warp layout: 2 x 4 grid of 32x64 tiles
    const int wm = wid >> 2;
    const int wn = wid & 3;
    const int arow_lane = wm * 32 + (lid & 15);
    const int a_uhalf   = lid >> 4;
    const int b_nlane   = wn * 64 + (lid & 7) + ((lid >> 4) << 3);
    const int b_uhalf   = (lid >> 3) & 1;

    float acc[2][8][4];
    #pragma unroll
    for (int a = 0; a < 2; ++a)
        #pragma unroll
        for (int b = 0; b < 8; ++b)
            #pragma unroll
            for (int c = 0; c < 4; ++c) acc[a][b][c] = 0.0f;

    float aacc = 0.0f;

// MMA over one K=32 chunk: A stage AST, B stage BST, k-half KH within B pair
#define MMA_CHUNK(AST, BST, KH)                                                     \
    {                                                                               \
        const uint32_t abase = sbase + OFF_A + (AST) * A_STG;                       \
        const uint32_t bbase = sbase + OFF_B + (BST) * B_STG;                       \
        _Pragma("unroll")                                                           \
        for (int ks = 0; ks < 2; ++ks) {                                            \
            uint32_t ah[2][4], bb[4][4];                                            \
            _Pragma("unroll")                                                       \
            for (int mt = 0; mt < 2; ++mt) {                                        \
                int r = arow_lane + mt * 16;                                        \
                uint32_t u = (uint32_t)((4 * (r & 1) + ks * 2 + a_uhalf)            \
                                        ^ ((r >> 1) & 7));                          \
                LDSM4(ah[mt], abase + (unsigned)(r >> 1) * 128 + (u << 4));         \
            }                                                                       \
            _Pragma("unroll")                                                       \
            for (int p = 0; p < 4; ++p) {                                           \
                int n = b_nlane + p * 16;                                           \
                uint32_t u = (uint32_t)(((KH) * 4 + ks * 2 + b_uhalf) ^ (n & 7));   \
                LDSM4(bb[p], bbase + (unsigned)n * 128 + (u << 4));                 \
            }                                                                       \
            _Pragma("unroll")                                                       \
            for (int mt = 0; mt < 2; ++mt)                                          \
                _Pragma("unroll")                                                   \
                for (int nt = 0; nt < 8; ++nt)                                      \
                    MMA16816(acc[mt][nt], ah[mt],                                   \
                             bb[nt >> 1][(nt & 1) * 2], bb[nt >> 1][(nt & 1) * 2 + 1]); \
        }                                                                           \
    }

    // ---------------- prologue: chunks 0-3 staged, 0-1 converted ----------------
    stage_h(sbase, 0, 0,  h, row0, tid);
    stage_h(sbase, 1, 32, h, row0, tid);
    stage_h(sbase, 2, 64, h, row0, tid);
    stage_h(sbase, 3, 96, h, row0, tid);
    stage_B(sbase, 0, 0, tid);
    CPCOMMIT();
    CPWAIT0();
    __syncthreads();
    convert_chunk(smem, 0, Ww, tid, aacc);
    convert_chunk(smem, 1, Ww, tid, aacc);
    __syncthreads();

    // ---------------- main loop: 8 iterations of 2 chunks, FULLY UNROLLED ----------------
    #pragma unroll
    for (int i = 0; i < 8; ++i) {
        const int c0 = 2 * i;
        if (i <= 5) {
            stage_h(sbase, (c0 + 4) & 3, (c0 + 4) * 32, h, row0, tid);
            stage_h(sbase, (c0 + 5) & 3, (c0 + 5) * 32, h, row0, tid);
        }
        if (i <= 6) stage_B(sbase, (i + 1) & 1, (i + 1) * 64, tid);
        CPCOMMIT();

        MMA_CHUNK(c0 & 3, i & 1, 0);
        if (i <= 6) convert_chunk(smem, c0 + 2, Ww, tid, aacc);
        MMA_CHUNK((c0 + 1) & 3, i & 1, 1);
        if (i <= 6) convert_chunk(smem, c0 + 3, Ww, tid, aacc);

        CPWAIT0();
        __syncthreads();
    }

    // ---------------- epilogue ----------------
    aacc += __shfl_xor_sync(0xffffffffu, aacc, 1);
    aacc += __shfl_xor_sync(0xffffffffu, aacc, 2);
    if ((tid & 3) == 0) alps[tid >> 2] = aacc;

    {
        #pragma unroll
        for (int mt = 0; mt < 2; ++mt) {
            float p0 = 0.0f, p1 = 0.0f;
            #pragma unroll
            for (int nt = 0; nt < 8; ++nt) {
                int col = wn * 64 + nt * 8 + 2 * (lid & 3);
                float bA = __ldg(b1 + col), bB = __ldg(b1 + col + 1);
                float wA = __ldg(W2 + col), wB = __ldg(W2 + col + 1);
                p0 += silu_f(acc[mt][nt][0] + bA) * wA + silu_f(acc[mt][nt][1] + bB) * wB;
                p1 += silu_f(acc[mt][nt][2] + bA) * wA + silu_f(acc[mt][nt][3] + bB) * wB;
            }
            p0 += __shfl_xor_sync(0xffffffffu, p0, 1);
            p0 += __shfl_xor_sync(0xffffffffu, p0, 2);
            p1 += __shfl_xor_sync(0xffffffffu, p1, 1);
            p1 += __shfl_xor_sync(0xffffffffu, p1, 2);
            if ((lid & 3) == 0) {
                int r = wm * 32 + mt * 16 + (lid >> 2);
                atomicAdd(&rsum[r], p0);
                atomicAdd(&rsum[r + 8], p1);
            }
        }
    }
    __syncthreads();

    if (tid < MROWS) {
        const int row = tid, grow = row0 + row;
        const float b2v = __ldg(b2), bwv = __ldg(bw);
        float val = (rsum[row] + b2v) * (alps[row] + bwv);
        int g = is64 ? (int)((const long long*)batch_raw)[grow]
                     : ((const int*)batch_raw)[grow];
        float tot = 0.0f;
        #pragma unroll
        for (int k2 = 0; k2 < 32; ++k2) {
            float vk = __shfl_sync(0xffffffffu, val, k2);
            int   gk = __shfl_sync(0xffffffffu, g, k2);
            if (gk == g) tot += vk;
        }
        int gp = __shfl_up_sync(0xffffffffu, g, 1);
        if (lid == 0 || g != gp) atomicAdd(out + g, tot);
    }
#undef MMA_CHUNK
}

// ---------------- launch ----------------
extern "C" void kernel_launch(void* const* d_in, const int* in_sizes, int n_in,
                              void* d_out, int out_size) {
    const float* h     = (const float*)d_in[0];
    const void*  batch = d_in[3];
    const float* W1    = (const float*)d_in[5];
    const float* b1    = (const float*)d_in[6];
    const float* W2    = (const float*)d_in[7];
    const float* b2    = (const float*)d_in[8];
    const float* Ww    = (const float*)d_in[9];
    const float* bw    = (const float*)d_in[10];
    float* out = (float*)d_out;

    cudaFuncSetAttribute(fused_mma_kernel,
                         cudaFuncAttributeMaxDynamicSharedMemorySize, SMEM_TOTAL);

    prep_kernel<<<(HHALF * HID) / 256, 256>>>(W1, out);

    int grid = N_ROWS / MROWS;   // 3125, exact
    fused_mma_kernel<<<grid, NTHREADS, SMEM_TOTAL>>>(h, batch, b1, W2, b2, Ww, bw, out);
}